// round 2
// baseline (speedup 1.0000x reference)
#include <cuda_runtime.h>
#include <cstdint>

// ============================================================================
// HGCN (2-layer hyperbolic GCN), c = 1 everywhere.
//
// Pipeline:
//   g1 = x @ W1^T                       (GEMM, raw x; encode scale folded later)
//   xt1 = rowwise(g1, ||x||)            (matvec scale + mobius_add(bias) + logmap0)
//   agg1 = scatter_add(w * xt1[src] -> dst)      (red.global.add.v4.f32)
//   h1, ||h1|| = rowwise(agg1)          (expmap0+proj+relu(logmap0)+expmap0+proj)
//   g2 = h1 @ W2^T
//   xt2 = rowwise(g2, ||h1||)
//   agg2 = scatter_add(...)
//   out  = rowwise(agg2)
// ============================================================================

#define BALL_MAXN 0.996f     // (1 - 4e-3)/sqrt(c)
#define EPSN      1e-15f
#define NODES_MAX 80000
#define DIM       64

__device__ float d_g  [NODES_MAX * DIM];
__device__ float d_xt [NODES_MAX * DIM];
__device__ float d_agg[NODES_MAX * DIM];
__device__ float d_h1 [NODES_MAX * DIM];
__device__ float d_xn [NODES_MAX];
__device__ float d_hb1[65];
__device__ float d_hb2[65];

__device__ __forceinline__ float wsum(float v) {
#pragma unroll
    for (int o = 16; o; o >>= 1) v += __shfl_xor_sync(0xffffffffu, v, o);
    return v;
}

__device__ __forceinline__ float artanh_f(float x) {
    x = fminf(fmaxf(x, -1.0f + 1e-7f), 1.0f - 1e-7f);
    return 0.5f * logf((1.0f + x) / (1.0f - x));
}

// ---------------------------------------------------------------------------
// hb = proj(expmap0(b)); hb[64] = ||hb||^2.  One block, 64 threads.
// ---------------------------------------------------------------------------
__global__ void init_hb_kernel(const float* __restrict__ b, float* __restrict__ hb) {
    __shared__ float sm[2];
    int t = threadIdx.x;  // 0..63
    float v = b[t];
    float ss = wsum(v * v);
    if ((t & 31) == 0) sm[t >> 5] = ss;
    __syncthreads();
    float tot = sm[0] + sm[1];
    __syncthreads();
    float nr = sqrtf(tot);
    float n  = fmaxf(nr, EPSN);
    float tn = tanhf(n);
    float e  = v * (tn / n);
    float en = fmaxf(tn * (nr / n), EPSN);   // ||e||
    float cf = (en > BALL_MAXN) ? (BALL_MAXN / en) : 1.0f;
    e *= cf;
    hb[t] = e;
    float ss2 = wsum(e * e);
    if ((t & 31) == 0) sm[t >> 5] = ss2;
    __syncthreads();
    if (t == 0) hb[64] = sm[0] + sm[1];
}

// ---------------------------------------------------------------------------
// GEMM: C[N,64] = A[N,K] @ W[64,K]^T.  Both K-contiguous row-major.
// BM=128, BN=64, BK=32, 256 threads, 8x4 register tile.
// ---------------------------------------------------------------------------
#define BM 128
#define BN 64
#define BK 32

__global__ __launch_bounds__(256, 2)
void gemm_kernel(const float* __restrict__ A, const float* __restrict__ W,
                 float* __restrict__ C, int N, int K) {
    __shared__ float As[BK][BM];  // k-major (transposed)
    __shared__ float Ws[BK][BN];

    int tid = threadIdx.x;
    int block_row = blockIdx.x * BM;
    int tr = tid >> 4;   // 0..15 -> rows tr*8 .. tr*8+7
    int tc = tid & 15;   // 0..15 -> cols tc*4 .. tc*4+3

    float acc[8][4];
#pragma unroll
    for (int i = 0; i < 8; i++)
#pragma unroll
        for (int j = 0; j < 4; j++) acc[i][j] = 0.0f;

    for (int k0 = 0; k0 < K; k0 += BK) {
        // load A tile: 128x32 floats = 1024 float4, 4 per thread
#pragma unroll
        for (int i = 0; i < 4; i++) {
            int idx = tid + i * 256;             // 0..1023
            int r   = idx >> 3;                  // 0..127
            int kq  = (idx & 7) << 2;            // 0,4,...,28
            int gr  = block_row + r;
            if (gr >= N) gr = N - 1;             // clamp (N is a multiple of BM here)
            float4 v = *(const float4*)(A + (size_t)gr * K + k0 + kq);
            As[kq + 0][r] = v.x; As[kq + 1][r] = v.y;
            As[kq + 2][r] = v.z; As[kq + 3][r] = v.w;
        }
        // load W tile: 64x32 floats = 512 float4, 2 per thread
#pragma unroll
        for (int i = 0; i < 2; i++) {
            int idx = tid + i * 256;             // 0..511
            int c   = idx >> 3;                  // 0..63
            int kq  = (idx & 7) << 2;
            float4 v = *(const float4*)(W + (size_t)c * K + k0 + kq);
            Ws[kq + 0][c] = v.x; Ws[kq + 1][c] = v.y;
            Ws[kq + 2][c] = v.z; Ws[kq + 3][c] = v.w;
        }
        __syncthreads();

#pragma unroll
        for (int kk = 0; kk < BK; kk++) {
            float4 a0 = *(const float4*)&As[kk][tr * 8];
            float4 a1 = *(const float4*)&As[kk][tr * 8 + 4];
            float4 b  = *(const float4*)&Ws[kk][tc * 4];
            float av[8] = {a0.x, a0.y, a0.z, a0.w, a1.x, a1.y, a1.z, a1.w};
            float bv[4] = {b.x, b.y, b.z, b.w};
#pragma unroll
            for (int i = 0; i < 8; i++)
#pragma unroll
                for (int j = 0; j < 4; j++)
                    acc[i][j] = fmaf(av[i], bv[j], acc[i][j]);
        }
        __syncthreads();
    }

#pragma unroll
    for (int i = 0; i < 8; i++) {
        int gr = block_row + tr * 8 + i;
        if (gr < N) {
            float4 o = make_float4(acc[i][0], acc[i][1], acc[i][2], acc[i][3]);
            *(float4*)(C + (size_t)gr * DIM + tc * 4) = o;
        }
    }
}

// ---------------------------------------------------------------------------
// Kernel A: per-row  mv = proj(mobius_matvec);  h = proj(mobius_add(mv, hb));
//                    xt = logmap0(h).   Warp per row, 2 dims per lane.
// mode 0: xarr = raw x [N,256] -> compute encode scale s and xn from ||x||.
// mode 1: xn given in xnarr, s = 1.
// ---------------------------------------------------------------------------
__global__ void kA_kernel(const float* __restrict__ g,
                          const float* __restrict__ xarr,
                          const float* __restrict__ xnarr,
                          int mode,
                          const float* __restrict__ hb,
                          float* __restrict__ xt_out, int N) {
    int row  = blockIdx.x * 8 + (threadIdx.x >> 5);
    int lane = threadIdx.x & 31;
    if (row >= N) return;

    float2 mx = *(const float2*)(g + (size_t)row * DIM + lane * 2);

    float xn, s;
    if (mode == 0) {
        const float4* xr = (const float4*)(xarr + (size_t)row * 256);
        float4 v1 = xr[lane * 2];
        float4 v2 = xr[lane * 2 + 1];
        float ss = v1.x*v1.x + v1.y*v1.y + v1.z*v1.z + v1.w*v1.w
                 + v2.x*v2.x + v2.y*v2.y + v2.z*v2.z + v2.w*v2.w;
        ss = wsum(ss);
        float nxr = sqrtf(ss);
        float nx  = fmaxf(nxr, EPSN);
        float t   = tanhf(nx);
        float en  = fmaxf(t * (nxr / nx), EPSN);         // ||expmap0(x)||
        float cf  = (en > BALL_MAXN) ? (BALL_MAXN / en) : 1.0f;
        s  = (t / nx) * cf;                               // h0 = s * x
        xn = fmaxf(en * cf, EPSN);                        // _norm(h0)
    } else {
        xn = xnarr[row];
        s  = 1.0f;
    }

    mx.x *= s; mx.y *= s;

    float mxn2 = wsum(mx.x * mx.x + mx.y * mx.y);
    float mxnr = sqrtf(mxn2);
    float mxn  = fmaxf(mxnr, EPSN);
    float tv   = tanhf(mxn / xn * artanh_f(xn));
    float rs   = tv / mxn;
    float rx = mx.x * rs, ry = mx.y * rs;

    // proj(res)
    float rn = fmaxf(mxnr * fabsf(rs), EPSN);
    if (rn > BALL_MAXN) { float f = BALL_MAXN / rn; rx *= f; ry *= f; }

    // mobius_add(res, hb)
    float hbx = hb[lane * 2], hby = hb[lane * 2 + 1];
    float y2  = hb[64];
    float x2  = wsum(rx * rx + ry * ry);
    float xy  = wsum(rx * hbx + ry * hby);
    float den = fmaxf(1.0f + 2.0f * xy + x2 * y2, EPSN);
    float ca  = (1.0f + 2.0f * xy + y2) / den;
    float cb  = (1.0f - x2) / den;
    float hx = ca * rx + cb * hbx;
    float hy = ca * ry + cb * hby;

    // proj
    float hn2 = wsum(hx * hx + hy * hy);
    float hnr = sqrtf(hn2);
    float hn  = fmaxf(hnr, EPSN);
    float cf2 = (hn > BALL_MAXN) ? (BALL_MAXN / hn) : 1.0f;
    hx *= cf2; hy *= cf2;

    // logmap0
    float hna = fmaxf(hnr * cf2, EPSN);
    float lc  = artanh_f(hna) / hna;
    float2 o = make_float2(hx * lc, hy * lc);
    *(float2*)(xt_out + (size_t)row * DIM + lane * 2) = o;
}

// ---------------------------------------------------------------------------
// Scatter: agg[dst[e]] += w[e] * xt[src[e]]  via red.global.add.v4.f32
// 16 threads per edge (one float4 each).
// ---------------------------------------------------------------------------
__device__ __forceinline__ void red_add_v4(float* p, float4 v) {
    asm volatile("red.global.add.v4.f32 [%0], {%1,%2,%3,%4};"
                 :: "l"(p), "f"(v.x), "f"(v.y), "f"(v.z), "f"(v.w) : "memory");
}

__global__ void scatter_kernel(const float* __restrict__ xt,
                               const int* __restrict__ src,
                               const int* __restrict__ dst,
                               const float* __restrict__ w,
                               float* __restrict__ agg, int E) {
    int item = blockIdx.x * blockDim.x + threadIdx.x;
    if (item >= E * 16) return;
    int e = item >> 4;
    int c = (item & 15) << 2;
    int sN = __ldg(&src[e]);
    int dN = __ldg(&dst[e]);
    float wt = __ldg(&w[e]);
    float4 v = *(const float4*)(xt + (size_t)sN * DIM + c);
    v.x *= wt; v.y *= wt; v.z *= wt; v.w *= wt;
    red_add_v4(agg + (size_t)dN * DIM + c, v);
}

__global__ void zero_kernel(float4* __restrict__ p, int n4) {
    int i = blockIdx.x * blockDim.x + threadIdx.x;
    if (i < n4) p[i] = make_float4(0.f, 0.f, 0.f, 0.f);
}

// ---------------------------------------------------------------------------
// Kernel C: per-row  h = proj(expmap0(agg)); xt = relu(logmap0(h));
//                    out = proj(expmap0(xt)).  Optionally store ||out||.
// ---------------------------------------------------------------------------
__global__ void kC_kernel(const float* __restrict__ agg,
                          float* __restrict__ out,
                          float* __restrict__ xn_out, int N) {
    int row  = blockIdx.x * 8 + (threadIdx.x >> 5);
    int lane = threadIdx.x & 31;
    if (row >= N) return;

    float2 a = *(const float2*)(agg + (size_t)row * DIM + lane * 2);

    float na2 = wsum(a.x * a.x + a.y * a.y);
    float nar = sqrtf(na2);
    float na  = fmaxf(nar, EPSN);
    float t   = tanhf(na);
    float f1  = t / na;
    float en  = fmaxf(t * (nar / na), EPSN);
    float c1  = (en > BALL_MAXN) ? (BALL_MAXN / en) : 1.0f;
    float hn  = fmaxf(en * c1, EPSN);
    float lco = artanh_f(hn) / hn * (f1 * c1);

    float lx = fmaxf(a.x * lco, 0.0f);   // relu(logmap0)
    float ly = fmaxf(a.y * lco, 0.0f);

    float nx2 = wsum(lx * lx + ly * ly);
    float nxr = sqrtf(nx2);
    float nx  = fmaxf(nxr, EPSN);
    float t2  = tanhf(nx);
    float f2  = t2 / nx;
    float en2 = fmaxf(t2 * (nxr / nx), EPSN);
    float c2  = (en2 > BALL_MAXN) ? (BALL_MAXN / en2) : 1.0f;

    float2 o = make_float2(lx * (f2 * c2), ly * (f2 * c2));
    *(float2*)(out + (size_t)row * DIM + lane * 2) = o;

    if (xn_out != nullptr && lane == 0)
        xn_out[row] = fmaxf(en2 * c2, EPSN);
}

// ---------------------------------------------------------------------------
// Launch
// ---------------------------------------------------------------------------
extern "C" void kernel_launch(void* const* d_in, const int* in_sizes, int n_in,
                              void* d_out, int out_size) {
    const float* x   = (const float*)d_in[0];
    const int*   src = (const int*)  d_in[1];
    const int*   dst = (const int*)  d_in[2];
    const float* ew  = (const float*)d_in[3];
    const float* W1  = (const float*)d_in[4];
    const float* b1  = (const float*)d_in[5];
    const float* W2  = (const float*)d_in[6];
    const float* b2  = (const float*)d_in[7];
    float* out = (float*)d_out;

    int N = in_sizes[0] / 256;
    int E = in_sizes[1];

    float *g, *xt, *agg, *h1, *xn, *hb1, *hb2;
    cudaGetSymbolAddress((void**)&g,   d_g);
    cudaGetSymbolAddress((void**)&xt,  d_xt);
    cudaGetSymbolAddress((void**)&agg, d_agg);
    cudaGetSymbolAddress((void**)&h1,  d_h1);
    cudaGetSymbolAddress((void**)&xn,  d_xn);
    cudaGetSymbolAddress((void**)&hb1, d_hb1);
    cudaGetSymbolAddress((void**)&hb2, d_hb2);

    int rowBlocks   = (N + 7) / 8;
    int gemmBlocks  = (N + BM - 1) / BM;
    int zeroBlocks  = (N * DIM / 4 + 255) / 256;
    int scatBlocks  = (E * 16 + 255) / 256;

    // bias constants
    init_hb_kernel<<<1, 64>>>(b1, hb1);
    init_hb_kernel<<<1, 64>>>(b2, hb2);

    // ---- layer 1 ----
    gemm_kernel<<<gemmBlocks, 256>>>(x, W1, g, N, 256);
    kA_kernel<<<rowBlocks, 256>>>(g, x, nullptr, 0, hb1, xt, N);
    zero_kernel<<<zeroBlocks, 256>>>((float4*)agg, N * DIM / 4);
    scatter_kernel<<<scatBlocks, 256>>>(xt, src, dst, ew, agg, E);
    kC_kernel<<<rowBlocks, 256>>>(agg, h1, xn, N);

    // ---- layer 2 ----
    gemm_kernel<<<gemmBlocks, 256>>>(h1, W2, g, N, 64);
    kA_kernel<<<rowBlocks, 256>>>(g, nullptr, xn, 1, hb2, xt, N);
    zero_kernel<<<zeroBlocks, 256>>>((float4*)agg, N * DIM / 4);
    scatter_kernel<<<scatBlocks, 256>>>(xt, src, dst, ew, agg, E);
    kC_kernel<<<rowBlocks, 256>>>(agg, out, nullptr, N);
}

// round 3
// speedup vs baseline: 1.2723x; 1.2723x over previous
#include <cuda_runtime.h>
#include <cstdint>

// ============================================================================
// HGCN (2-layer hyperbolic GCN), c = 1.
//
// R3 pipeline (CSR-gather instead of atomic scatter; fused epilogues):
//   CSR build (deg hist -> scan -> fill)                      [once, reused 2x]
//   g1 = s(||x||) * (x @ W1^T)   (fused encode scale + xn in GEMM epilogue)
//   xt1 = kA(g1, xn, hb1)        (mobius_matvec tail + mobius_add + logmap0)
//   h1, xn = gather_kC(xt1)      (CSR gather + expmap0/proj/relu/logmap/expmap)
//   g2 = h1 @ W2^T
//   xt2 = kA(g2, xn, hb2)
//   out = gather_kC(xt2)
// ============================================================================

#define BALL_MAXN 0.996f     // (1 - 4e-3)/sqrt(c)
#define EPSN      1e-15f
#define NODES_MAX 80000
#define E_MAX     1300000
#define DIM       64

__device__ float d_g  [NODES_MAX * DIM];
__device__ float d_xt [NODES_MAX * DIM];
__device__ float d_h1 [NODES_MAX * DIM];
__device__ float d_xn [NODES_MAX];
__device__ float d_hb1[65];
__device__ float d_hb2[65];
__device__ int   d_deg[NODES_MAX];
__device__ int   d_off[NODES_MAX];
__device__ int   d_cur[NODES_MAX];
__device__ int   d_bsum[256];
__device__ int   d_bsumex[256];
__device__ int2  d_edata[E_MAX];

__device__ __forceinline__ float wsum(float v) {
#pragma unroll
    for (int o = 16; o; o >>= 1) v += __shfl_xor_sync(0xffffffffu, v, o);
    return v;
}

__device__ __forceinline__ float artanh_f(float x) {
    x = fminf(fmaxf(x, -1.0f + 1e-7f), 1.0f - 1e-7f);
    return 0.5f * logf((1.0f + x) / (1.0f - x));
}

// ---------------------------------------------------------------------------
// hb = proj(expmap0(b)); hb[64] = ||hb||^2.  One block, 64 threads.
// ---------------------------------------------------------------------------
__global__ void init_hb_kernel(const float* __restrict__ b, float* __restrict__ hb) {
    __shared__ float sm[2];
    int t = threadIdx.x;
    float v = b[t];
    float ss = wsum(v * v);
    if ((t & 31) == 0) sm[t >> 5] = ss;
    __syncthreads();
    float tot = sm[0] + sm[1];
    __syncthreads();
    float nr = sqrtf(tot);
    float n  = fmaxf(nr, EPSN);
    float tn = tanhf(n);
    float e  = v * (tn / n);
    float en = fmaxf(tn * (nr / n), EPSN);
    float cf = (en > BALL_MAXN) ? (BALL_MAXN / en) : 1.0f;
    e *= cf;
    hb[t] = e;
    float ss2 = wsum(e * e);
    if ((t & 31) == 0) sm[t >> 5] = ss2;
    __syncthreads();
    if (t == 0) hb[64] = sm[0] + sm[1];
}

// ---------------------------------------------------------------------------
// CSR build
// ---------------------------------------------------------------------------
__global__ void zero_deg_kernel(int* __restrict__ deg, int N) {
    int i = blockIdx.x * blockDim.x + threadIdx.x;
    if (i < N) deg[i] = 0;
}

__global__ void hist_kernel(const int* __restrict__ dst, int* __restrict__ deg, int E) {
    int e = blockIdx.x * blockDim.x + threadIdx.x;
    if (e < E) atomicAdd(&deg[dst[e]], 1);
}

// Block of 256 threads scans 1024 elements (4 per thread).
__global__ void scan1_kernel(const int* __restrict__ deg, int* __restrict__ off,
                             int* __restrict__ bsum, int N) {
    __shared__ int sh[256];
    int tid  = threadIdx.x;
    int base = blockIdx.x * 1024;
    int idx0 = base + tid * 4;
    int v[4];
#pragma unroll
    for (int j = 0; j < 4; j++) {
        int id = idx0 + j;
        v[j] = (id < N) ? deg[id] : 0;
    }
    int t = v[0] + v[1] + v[2] + v[3];
    sh[tid] = t;
    __syncthreads();
#pragma unroll
    for (int o = 1; o < 256; o <<= 1) {
        int u = (tid >= o) ? sh[tid - o] : 0;
        __syncthreads();
        sh[tid] += u;
        __syncthreads();
    }
    int excl = sh[tid] - t;
    int run = excl;
#pragma unroll
    for (int j = 0; j < 4; j++) {
        int id = idx0 + j;
        if (id < N) off[id] = run;
        run += v[j];
    }
    if (tid == 255) bsum[blockIdx.x] = sh[255];
}

__global__ void scan2_kernel(const int* __restrict__ bsum, int* __restrict__ bsumex, int B) {
    __shared__ int sh[256];
    int tid = threadIdx.x;
    int t = (tid < B) ? bsum[tid] : 0;
    sh[tid] = t;
    __syncthreads();
#pragma unroll
    for (int o = 1; o < 256; o <<= 1) {
        int u = (tid >= o) ? sh[tid - o] : 0;
        __syncthreads();
        sh[tid] += u;
        __syncthreads();
    }
    if (tid < B) bsumex[tid] = sh[tid] - t;
}

__global__ void scan3_kernel(int* __restrict__ off, int* __restrict__ cur,
                             const int* __restrict__ bsumex, int N) {
    int i = blockIdx.x * blockDim.x + threadIdx.x;
    if (i < N) {
        int v = off[i] + bsumex[i >> 10];
        off[i] = v;
        cur[i] = v;
    }
}

__global__ void fill_kernel(const int* __restrict__ src, const int* __restrict__ dst,
                            const float* __restrict__ w, int* __restrict__ cur,
                            int2* __restrict__ ed, int E) {
    int e = blockIdx.x * blockDim.x + threadIdx.x;
    if (e >= E) return;
    int d = dst[e];
    int pos = atomicAdd(&cur[d], 1);
    ed[pos] = make_int2(src[e], __float_as_int(w[e]));
}

// ---------------------------------------------------------------------------
// GEMM: C[N,64] = A[N,K] @ W[64,K]^T.  MODE 0: fused encode scale + xn out.
// BM=128, BN=64, BK=32, 256 threads, 8x4 register tile.
// ---------------------------------------------------------------------------
#define BM 128
#define BN 64
#define BK 32

template <int MODE>
__global__ __launch_bounds__(256, 2)
void gemm_kernel(const float* __restrict__ A, const float* __restrict__ W,
                 float* __restrict__ C, float* __restrict__ xn_out, int N, int K) {
    __shared__ float As[BK][BM];  // k-major
    __shared__ float Ws[BK][BN];
    __shared__ float sred[4][256];
    __shared__ float snorm[BM];

    int tid = threadIdx.x;
    int block_row = blockIdx.x * BM;
    int tr = tid >> 4;   // rows tr*8 .. +7
    int tc = tid & 15;   // cols tc*4 .. +3

    float acc[8][4];
#pragma unroll
    for (int i = 0; i < 8; i++)
#pragma unroll
        for (int j = 0; j < 4; j++) acc[i][j] = 0.0f;
    float ssl[4] = {0.f, 0.f, 0.f, 0.f};

    for (int k0 = 0; k0 < K; k0 += BK) {
#pragma unroll
        for (int i = 0; i < 4; i++) {
            int idx = tid + i * 256;
            int r   = idx >> 3;
            int kq  = (idx & 7) << 2;
            int gr  = block_row + r;
            if (gr >= N) gr = N - 1;
            float4 v = *(const float4*)(A + (size_t)gr * K + k0 + kq);
            As[kq + 0][r] = v.x; As[kq + 1][r] = v.y;
            As[kq + 2][r] = v.z; As[kq + 3][r] = v.w;
            if (MODE == 0)
                ssl[i] += v.x * v.x + v.y * v.y + v.z * v.z + v.w * v.w;
        }
#pragma unroll
        for (int i = 0; i < 2; i++) {
            int idx = tid + i * 256;
            int c   = idx >> 3;
            int kq  = (idx & 7) << 2;
            float4 v = *(const float4*)(W + (size_t)c * K + k0 + kq);
            Ws[kq + 0][c] = v.x; Ws[kq + 1][c] = v.y;
            Ws[kq + 2][c] = v.z; Ws[kq + 3][c] = v.w;
        }
        __syncthreads();

#pragma unroll
        for (int kk = 0; kk < BK; kk++) {
            float4 a0 = *(const float4*)&As[kk][tr * 8];
            float4 a1 = *(const float4*)&As[kk][tr * 8 + 4];
            float4 b  = *(const float4*)&Ws[kk][tc * 4];
            float av[8] = {a0.x, a0.y, a0.z, a0.w, a1.x, a1.y, a1.z, a1.w};
            float bv[4] = {b.x, b.y, b.z, b.w};
#pragma unroll
            for (int i = 0; i < 8; i++)
#pragma unroll
                for (int j = 0; j < 4; j++)
                    acc[i][j] = fmaf(av[i], bv[j], acc[i][j]);
        }
        __syncthreads();
    }

    if (MODE == 0) {
        // reduce per-row x sum-of-squares: row r held by 8 threads (k-chunks)
        sred[0][tid] = ssl[0]; sred[1][tid] = ssl[1];
        sred[2][tid] = ssl[2]; sred[3][tid] = ssl[3];
        __syncthreads();
        if (tid < 128) {
            int r   = tid;
            int grp = r >> 5;
            int t0  = (r & 31) << 3;
            float s2 = 0.0f;
#pragma unroll
            for (int j = 0; j < 8; j++) s2 += sred[grp][t0 + j];
            snorm[r] = s2;
        }
        __syncthreads();
    }

#pragma unroll
    for (int i = 0; i < 8; i++) {
        int r  = tr * 8 + i;
        int gr = block_row + r;
        if (gr >= N) continue;
        float sc = 1.0f;
        if (MODE == 0) {
            float nxr = sqrtf(snorm[r]);
            float nx  = fmaxf(nxr, EPSN);
            float t   = tanhf(nx);
            float en  = fmaxf(t * (nxr / nx), EPSN);    // ||expmap0(x)||
            float cf  = (en > BALL_MAXN) ? (BALL_MAXN / en) : 1.0f;
            sc = (t / nx) * cf;                          // h0 = sc * x
            if (tc == 0) xn_out[gr] = fmaxf(en * cf, EPSN);
        }
        float4 o = make_float4(acc[i][0] * sc, acc[i][1] * sc,
                               acc[i][2] * sc, acc[i][3] * sc);
        *(float4*)(C + (size_t)gr * DIM + tc * 4) = o;
    }
}

// ---------------------------------------------------------------------------
// kA: mv = proj(mobius_matvec tail); h = proj(mobius_add(mv, hb)); xt = logmap0.
// Warp per row, 2 dims per lane. xn (= _norm of layer input) given per row.
// ---------------------------------------------------------------------------
__global__ void kA_kernel(const float* __restrict__ g,
                          const float* __restrict__ xnarr,
                          const float* __restrict__ hb,
                          float* __restrict__ xt_out, int N) {
    int row  = blockIdx.x * 8 + (threadIdx.x >> 5);
    int lane = threadIdx.x & 31;
    if (row >= N) return;

    float2 mx = *(const float2*)(g + (size_t)row * DIM + lane * 2);
    float xn = xnarr[row];

    float mxn2 = wsum(mx.x * mx.x + mx.y * mx.y);
    float mxnr = sqrtf(mxn2);
    float mxn  = fmaxf(mxnr, EPSN);
    float tv   = tanhf(mxn / xn * artanh_f(xn));
    float rs   = tv / mxn;
    float rx = mx.x * rs, ry = mx.y * rs;

    float rn = fmaxf(mxnr * fabsf(rs), EPSN);
    if (rn > BALL_MAXN) { float f = BALL_MAXN / rn; rx *= f; ry *= f; }

    float hbx = hb[lane * 2], hby = hb[lane * 2 + 1];
    float y2  = hb[64];
    float x2  = wsum(rx * rx + ry * ry);
    float xy  = wsum(rx * hbx + ry * hby);
    float den = fmaxf(1.0f + 2.0f * xy + x2 * y2, EPSN);
    float ca  = (1.0f + 2.0f * xy + y2) / den;
    float cb  = (1.0f - x2) / den;
    float hx = ca * rx + cb * hbx;
    float hy = ca * ry + cb * hby;

    float hn2 = wsum(hx * hx + hy * hy);
    float hnr = sqrtf(hn2);
    float hn  = fmaxf(hnr, EPSN);
    float cf2 = (hn > BALL_MAXN) ? (BALL_MAXN / hn) : 1.0f;
    hx *= cf2; hy *= cf2;

    float hna = fmaxf(hnr * cf2, EPSN);
    float lc  = artanh_f(hna) / hna;
    float2 o = make_float2(hx * lc, hy * lc);
    *(float2*)(xt_out + (size_t)row * DIM + lane * 2) = o;
}

// ---------------------------------------------------------------------------
// Gather + kC: agg = sum_e w*xt[src] over CSR list of this dst node, then
// h = proj(expmap0(agg)); xt = relu(logmap0(h)); out = proj(expmap0(xt)).
// Warp per node, 2 dims per lane.
// ---------------------------------------------------------------------------
__global__ void gather_kc_kernel(const float* __restrict__ xt,
                                 const int2* __restrict__ ed,
                                 const int* __restrict__ off,
                                 const int* __restrict__ deg,
                                 float* __restrict__ out,
                                 float* __restrict__ xn_out, int N) {
    int row  = blockIdx.x * 8 + (threadIdx.x >> 5);
    int lane = threadIdx.x & 31;
    if (row >= N) return;

    int beg = off[row];
    int dc  = deg[row];

    float ax = 0.0f, ay = 0.0f;
    for (int i0 = 0; i0 < dc; i0 += 32) {
        int i = i0 + lane;
        int2 e = (i < dc) ? __ldg(&ed[beg + i]) : make_int2(0, 0);
        int cnt = min(32, dc - i0);
        for (int j = 0; j < cnt; j++) {
            int   s  = __shfl_sync(0xffffffffu, e.x, j);
            float wt = __int_as_float(__shfl_sync(0xffffffffu, e.y, j));
            float2 v = *(const float2*)(xt + (size_t)s * DIM + lane * 2);
            ax = fmaf(wt, v.x, ax);
            ay = fmaf(wt, v.y, ay);
        }
    }

    // kC math
    float na2 = wsum(ax * ax + ay * ay);
    float nar = sqrtf(na2);
    float na  = fmaxf(nar, EPSN);
    float t   = tanhf(na);
    float f1  = t / na;
    float en  = fmaxf(t * (nar / na), EPSN);
    float c1  = (en > BALL_MAXN) ? (BALL_MAXN / en) : 1.0f;
    float hn  = fmaxf(en * c1, EPSN);
    float lco = artanh_f(hn) / hn * (f1 * c1);

    float lx = fmaxf(ax * lco, 0.0f);
    float ly = fmaxf(ay * lco, 0.0f);

    float nx2 = wsum(lx * lx + ly * ly);
    float nxr = sqrtf(nx2);
    float nx  = fmaxf(nxr, EPSN);
    float t2  = tanhf(nx);
    float f2  = t2 / nx;
    float en2 = fmaxf(t2 * (nxr / nx), EPSN);
    float c2  = (en2 > BALL_MAXN) ? (BALL_MAXN / en2) : 1.0f;

    float2 o = make_float2(lx * (f2 * c2), ly * (f2 * c2));
    *(float2*)(out + (size_t)row * DIM + lane * 2) = o;

    if (xn_out != nullptr && lane == 0)
        xn_out[row] = fmaxf(en2 * c2, EPSN);
}

// ---------------------------------------------------------------------------
// Launch
// ---------------------------------------------------------------------------
extern "C" void kernel_launch(void* const* d_in, const int* in_sizes, int n_in,
                              void* d_out, int out_size) {
    const float* x   = (const float*)d_in[0];
    const int*   src = (const int*)  d_in[1];
    const int*   dst = (const int*)  d_in[2];
    const float* ew  = (const float*)d_in[3];
    const float* b1  = (const float*)d_in[5];
    const float* W1  = (const float*)d_in[4];
    const float* W2  = (const float*)d_in[6];
    const float* b2  = (const float*)d_in[7];
    float* out = (float*)d_out;

    int N = in_sizes[0] / 256;
    int E = in_sizes[1];

    float *g, *xt, *h1, *xn, *hb1, *hb2;
    int *deg, *off, *cur, *bsum, *bsumex;
    int2* edata;
    cudaGetSymbolAddress((void**)&g,      d_g);
    cudaGetSymbolAddress((void**)&xt,     d_xt);
    cudaGetSymbolAddress((void**)&h1,     d_h1);
    cudaGetSymbolAddress((void**)&xn,     d_xn);
    cudaGetSymbolAddress((void**)&hb1,    d_hb1);
    cudaGetSymbolAddress((void**)&hb2,    d_hb2);
    cudaGetSymbolAddress((void**)&deg,    d_deg);
    cudaGetSymbolAddress((void**)&off,    d_off);
    cudaGetSymbolAddress((void**)&cur,    d_cur);
    cudaGetSymbolAddress((void**)&bsum,   d_bsum);
    cudaGetSymbolAddress((void**)&bsumex, d_bsumex);
    cudaGetSymbolAddress((void**)&edata,  d_edata);

    int rowBlocks  = (N + 7) / 8;
    int gemmBlocks = (N + BM - 1) / BM;
    int nBlocks256 = (N + 255) / 256;
    int eBlocks256 = (E + 255) / 256;
    int scanBlocks = (N + 1023) / 1024;

    // bias constants
    init_hb_kernel<<<1, 64>>>(b1, hb1);
    init_hb_kernel<<<1, 64>>>(b2, hb2);

    // ---- CSR build (shared by both layers) ----
    zero_deg_kernel<<<nBlocks256, 256>>>(deg, N);
    hist_kernel<<<eBlocks256, 256>>>(dst, deg, E);
    scan1_kernel<<<scanBlocks, 256>>>(deg, off, bsum, N);
    scan2_kernel<<<1, 256>>>(bsum, bsumex, scanBlocks);
    scan3_kernel<<<nBlocks256, 256>>>(off, cur, bsumex, N);
    fill_kernel<<<eBlocks256, 256>>>(src, dst, ew, cur, edata, E);

    // ---- layer 1 ----
    gemm_kernel<0><<<gemmBlocks, 256>>>(x, W1, g, xn, N, 256);
    kA_kernel<<<rowBlocks, 256>>>(g, xn, hb1, xt, N);
    gather_kc_kernel<<<rowBlocks, 256>>>(xt, edata, off, deg, h1, xn, N);

    // ---- layer 2 ----
    gemm_kernel<1><<<gemmBlocks, 256>>>(h1, W2, g, nullptr, N, 64);
    kA_kernel<<<rowBlocks, 256>>>(g, xn, hb2, xt, N);
    gather_kc_kernel<<<rowBlocks, 256>>>(xt, edata, off, deg, out, nullptr, N);
}